// round 4
// baseline (speedup 1.0000x reference)
#include <cuda_runtime.h>
#include <cuda_bf16.h>
#include <math.h>

typedef unsigned long long ull;

#define NMAX 50000
#define FD   256
#define KMIX 5

// ---------------- scratch (allocation-free: __device__ globals) ----------------
__device__ float g_SRC[(size_t)NMAX * 512];   // per-node payload: [0:256)=xm, [256:512)=mask
__device__ float g_ACC[(size_t)NMAX * 512];   // accumulated (self + in-edges)
__device__ float g_DEG[NMAX];                 // 1 + in-degree
__device__ float g_GAMMA[KMIX * NMAX];        // softmax mixture weights
__device__ float g_WK[KMIX * FD * FD];        // means[k,f]*W[f,o]
__device__ float g_VK[KMIX * FD * FD];        // exp(logvars[k,f])*W[f,o]^2
__device__ float g_INVVAR[KMIX * FD];         // exp(-logvars)
__device__ int   g_maskByte;                  // 1 if mask stored as 1-byte elems
__device__ int   g_edges64;                   // 1 if edges stored as int64

// ---------------- f32x2 helpers ----------------
__device__ __forceinline__ ull pk2(float a, float b) {
    ull r;
    asm("mov.b64 %0, {%1, %2};" : "=l"(r) : "f"(a), "f"(b));
    return r;
}
__device__ __forceinline__ void up2(ull v, float& a, float& b) {
    asm("mov.b64 {%0, %1}, %2;" : "=f"(a), "=f"(b) : "l"(v));
}
__device__ __forceinline__ ull fma2(ull a, ull b, ull c) {
    ull d;
    asm("fma.rn.f32x2 %0, %1, %2, %3;" : "=l"(d) : "l"(a), "l"(b), "l"(c));
    return d;
}

__device__ __forceinline__ float ex_relu(float mu, float sg) {
    if (sg == 0.0f) return fmaxf(mu, 0.0f);
    float ss = sqrtf(sg);
    float w  = mu / ss;
    float pdf = __expf(-0.5f * w * w) * 0.3989422804014327f;   // 1/sqrt(2*pi)
    return ss * (pdf + 0.5f * w * (1.0f + erff(w * 0.7071067811865476f)));
}

// ---------------- K0: dtype detection ----------------
__global__ void k_detect(const unsigned char* maskb, const unsigned int* edgesw) {
    __shared__ int fM, fE;
    if (threadIdx.x == 0) { fM = 0; fE = 0; }
    __syncthreads();
    int lm = 0, le = 0;
    for (int i = threadIdx.x; i < 4096; i += 256) {
        if (maskb[4 * i + 1] != 0) lm = 1;       // bool layout: elem bytes at all offsets
        if (edgesw[2 * i + 1] != 0) le = 1;      // int32 layout: odd words are node ids
    }
    if (lm) atomicOr(&fM, 1);
    if (le) atomicOr(&fE, 1);
    __syncthreads();
    if (threadIdx.x == 0) { g_maskByte = fM; g_edges64 = (fE == 0); }
}

// ---------------- K1: per-k weights + invvar ----------------
__global__ void k_weights(const float* __restrict__ W, const float* __restrict__ means,
                          const float* __restrict__ logvars) {
    int idx = blockIdx.x * 256 + threadIdx.x;            // < 5*65536
    int k = idx >> 16;
    int r = idx & 65535;
    int f = r >> 8;
    float w = W[r];
    g_WK[idx] = means[k * FD + f] * w;
    g_VK[idx] = expf(logvars[k * FD + f]) * w * w;
    if (idx < KMIX * FD) g_INVVAR[idx] = expf(-logvars[idx]);
}

// ---------------- K2: node init (xm, mask, self-term, gamma) ----------------
__global__ void k_init(const float* __restrict__ x, const void* __restrict__ mask,
                       const float* __restrict__ logp, const float* __restrict__ means,
                       int Nn) {
    int n = blockIdx.x;
    int f = threadIdx.x;
    int lane = f & 31, wid = f >> 5;
    size_t idx = (size_t)n * FD + f;

    int m;
    if (g_maskByte) m = ((const unsigned char*)mask)[idx] != 0;
    else            m = ((const unsigned int*)mask)[idx] != 0;

    float xv = x[idx];
    float xm = m ? 0.0f : xv;
    float mf = (float)m;
    size_t b = (size_t)n * 512;
    g_SRC[b + f] = xm;        g_SRC[b + 256 + f] = mf;
    g_ACC[b + f] = xm;        g_ACC[b + 256 + f] = mf;

    float s[KMIX];
#pragma unroll
    for (int k = 0; k < KMIX; k++) {
        float d = xv - means[k * FD + f];
        s[k] = m ? 0.0f : d * d * g_INVVAR[k * FD + f];
    }
#pragma unroll
    for (int k = 0; k < KMIX; k++)
#pragma unroll
        for (int off = 16; off; off >>= 1)
            s[k] += __shfl_down_sync(0xffffffffu, s[k], off);

    __shared__ float red[KMIX][8];
    if (lane == 0)
#pragma unroll
        for (int k = 0; k < KMIX; k++) red[k][wid] = s[k];
    __syncthreads();
    if (f == 0) {
        float li[KMIX], mx = -1e30f;
#pragma unroll
        for (int k = 0; k < KMIX; k++) {
            float S = 0.0f;
#pragma unroll
            for (int w = 0; w < 8; w++) S += red[k][w];
            li[k] = logp[k] - 0.5f * S;
            mx = fmaxf(mx, li[k]);
        }
        float se = 0.0f, ev[KMIX];
#pragma unroll
        for (int k = 0; k < KMIX; k++) { ev[k] = __expf(li[k] - mx); se += ev[k]; }
        float inv = 1.0f / se;
#pragma unroll
        for (int k = 0; k < KMIX; k++) g_GAMMA[(size_t)k * Nn + n] = ev[k] * inv;
        g_DEG[n] = 1.0f;
    }
}

// ---------------- K3: edge scatter (vectorized reductions) ----------------
__global__ void k_scatter(const void* __restrict__ edges, int E) {
    int tid = threadIdx.x;
    long long e = (long long)blockIdx.x * 2 + (tid >> 7);
    if (e >= E) return;
    int j = tid & 127;

    int s, d;
    if (g_edges64) {
        s = (int)((const long long*)edges)[e];
        d = (int)((const long long*)edges)[(size_t)E + e];
    } else {
        s = ((const int*)edges)[e];
        d = ((const int*)edges)[(size_t)E + e];
    }

    const float4* sp = (const float4*)(g_SRC + (size_t)s * 512);
    float4 v = __ldg(sp + j);
    float* dp = g_ACC + (size_t)d * 512 + (size_t)j * 4;
    asm volatile("red.global.add.v4.f32 [%0], {%1,%2,%3,%4};"
                 :: "l"(dp), "f"(v.x), "f"(v.y), "f"(v.z), "f"(v.w) : "memory");
    if (j == 0) atomicAdd(&g_DEG[d], 1.0f);
}

// ---------------- K4: fused 11-way GEMM + ex_relu + mixture ----------------
#define CTS 65
#define XTS 68
__global__ void __launch_bounds__(256, 2)
k_gemm(const float* __restrict__ W, const float* __restrict__ bias,
       float* __restrict__ out, int Nn) {
    extern __shared__ float sm[];
    float* Ct = sm;                      // [256][65]  C matrix tile (f-major)
    float* Wa = sm + 256 * CTS;          // [64][64]   weight chunk
    float* Xt = Wa + 64 * 64;            // [64][68]   A chunk / V-weight chunk

    int tid = threadIdx.x;
    int tx = tid & 15, ty = tid >> 4;
    int node0 = blockIdx.x * 64;
    int bo = blockIdx.y * 64;
    int o0 = bo + tx * 4;

    int nn[4];
#pragma unroll
    for (int i = 0; i < 4; i++) {
        int n = node0 + ty * 4 + i;
        nn[i] = n < Nn ? n : Nn - 1;
    }
    float bb[4];
#pragma unroll
    for (int j = 0; j < 4; j++) bb[j] = bias[o0 + j];
    float dg[4];
#pragma unroll
    for (int i = 0; i < 4; i++) dg[i] = g_DEG[nn[i]];

    // load persistent C tile
    for (int t = tid; t < 64 * 256; t += 256) {
        int f = t & 255, n = t >> 8;
        int gn = node0 + n; if (gn >= Nn) gn = Nn - 1;
        Ct[f * CTS + n] = g_ACC[(size_t)gn * 512 + 256 + f];
    }

    ull P[8], OA[8];
#pragma unroll
    for (int i = 0; i < 8; i++) { P[i] = 0; OA[i] = 0; }

    // ---- phase A: P = A @ W ----
    for (int fc = 0; fc < 256; fc += 64) {
        __syncthreads();
        for (int t = tid; t < 4096; t += 256) {
            int fr = t & 63, n = t >> 6;
            int gn = node0 + n; if (gn >= Nn) gn = Nn - 1;
            Xt[fr * XTS + n] = g_ACC[(size_t)gn * 512 + fc + fr];
        }
        for (int t = tid; t < 1024; t += 256) {
            int o4 = (t & 15) * 4, fr = t >> 4;
            *(float4*)&Wa[fr * 64 + o4] =
                *(const float4*)&W[(size_t)(fc + fr) * 256 + bo + o4];
        }
        __syncthreads();
#pragma unroll 8
        for (int fr = 0; fr < 64; fr++) {
            ull b0 = *(ull*)&Wa[fr * 64 + tx * 4];
            ull b1 = *(ull*)&Wa[fr * 64 + tx * 4 + 2];
#pragma unroll
            for (int i = 0; i < 4; i++) {
                float av = Xt[fr * XTS + ty * 4 + i];
                ull a2 = pk2(av, av);
                P[i * 2]     = fma2(a2, b0, P[i * 2]);
                P[i * 2 + 1] = fma2(a2, b1, P[i * 2 + 1]);
            }
        }
    }

    // ---- phase B: per-k Q = C@Wk, S = C@Vk, fused epilogue ----
    for (int k = 0; k < KMIX; k++) {
        ull Q[8], S[8];
#pragma unroll
        for (int i = 0; i < 8; i++) { Q[i] = 0; S[i] = 0; }
        const float* WKp = g_WK + ((size_t)k << 16);
        const float* VKp = g_VK + ((size_t)k << 16);

        for (int fc = 0; fc < 256; fc += 64) {
            __syncthreads();
            for (int t = tid; t < 1024; t += 256) {
                int o4 = (t & 15) * 4, fr = t >> 4;
                size_t g = (size_t)(fc + fr) * 256 + bo + o4;
                *(float4*)&Wa[fr * 64 + o4]  = *(const float4*)&WKp[g];
                *(float4*)&Xt[fr * XTS + o4] = *(const float4*)&VKp[g];
            }
            __syncthreads();
#pragma unroll 8
            for (int fr = 0; fr < 64; fr++) {
                ull bw0 = *(ull*)&Wa[fr * 64 + tx * 4];
                ull bw1 = *(ull*)&Wa[fr * 64 + tx * 4 + 2];
                ull bv0 = *(ull*)&Xt[fr * XTS + tx * 4];
                ull bv1 = *(ull*)&Xt[fr * XTS + tx * 4 + 2];
#pragma unroll
                for (int i = 0; i < 4; i++) {
                    float av = Ct[(fc + fr) * CTS + ty * 4 + i];
                    ull a2 = pk2(av, av);
                    Q[i * 2]     = fma2(a2, bw0, Q[i * 2]);
                    Q[i * 2 + 1] = fma2(a2, bw1, Q[i * 2 + 1]);
                    S[i * 2]     = fma2(a2, bv0, S[i * 2]);
                    S[i * 2 + 1] = fma2(a2, bv1, S[i * 2 + 1]);
                }
            }
        }
        // epilogue for this k
#pragma unroll
        for (int i = 0; i < 4; i++) {
            float gam = g_GAMMA[(size_t)k * Nn + nn[i]];
#pragma unroll
            for (int jj = 0; jj < 2; jj++) {
                float p0, p1, q0, q1, s0, s1, a0, a1;
                up2(P[i * 2 + jj], p0, p1);
                up2(Q[i * 2 + jj], q0, q1);
                up2(S[i * 2 + jj], s0, s1);
                float mu0 = p0 + q0 + dg[i] * bb[jj * 2];
                float mu1 = p1 + q1 + dg[i] * bb[jj * 2 + 1];
                float v0 = ex_relu(mu0, s0);
                float v1 = ex_relu(mu1, s1);
                up2(OA[i * 2 + jj], a0, a1);
                OA[i * 2 + jj] = pk2(a0 + gam * v0, a1 + gam * v1);
            }
        }
    }

    // store
#pragma unroll
    for (int i = 0; i < 4; i++) {
        int n = node0 + ty * 4 + i;
        if (n < Nn) {
            float a, b, c, d;
            up2(OA[i * 2], a, b);
            up2(OA[i * 2 + 1], c, d);
            *(float4*)&out[(size_t)n * 256 + o0] = make_float4(a, b, c, d);
        }
    }
}

// ---------------- launch ----------------
extern "C" void kernel_launch(void* const* d_in, const int* in_sizes, int n_in,
                              void* d_out, int out_size) {
    const float* x       = (const float*)d_in[0];
    const void*  edges   = (const void*) d_in[1];
    const void*  mask    = (const void*) d_in[2];
    const float* logp    = (const float*)d_in[3];
    const float* means   = (const float*)d_in[4];
    const float* logvars = (const float*)d_in[5];
    const float* W       = (const float*)d_in[6];
    const float* bias    = (const float*)d_in[7];
    float* out = (float*)d_out;

    int Nn = in_sizes[0] / FD;      // 50000
    int E  = in_sizes[1] / 2;       // 1600000

    k_detect<<<1, 256>>>((const unsigned char*)mask, (const unsigned int*)edges);
    k_weights<<<(KMIX * FD * FD) / 256, 256>>>(W, means, logvars);
    k_init<<<Nn, 256>>>(x, mask, logp, means, Nn);
    k_scatter<<<(E + 1) / 2, 256>>>(edges, E);

    static int smem_set = 0;
    int smem = (256 * CTS + 64 * 64 + 64 * XTS) * 4;   // 100352 B
    if (!smem_set) {
        cudaFuncSetAttribute(k_gemm, cudaFuncAttributeMaxDynamicSharedMemorySize, smem);
        smem_set = 1;
    }
    dim3 grid((Nn + 63) / 64, 4);
    k_gemm<<<grid, 256, smem>>>(W, bias, out, Nn);
}

// round 6
// speedup vs baseline: 1.7853x; 1.7853x over previous
#include <cuda_runtime.h>
#include <cuda_bf16.h>
#include <cuda_fp16.h>
#include <math.h>
#include <stdint.h>

typedef unsigned int uint32;
typedef unsigned long long ull;

#define NMAX 50000
#define FD   256
#define KMIX 5

// ---------------- scratch (allocation-free: __device__ globals) ----------------
__device__ float  g_SRCX[(size_t)NMAX * FD];    // masked x (xm) per node
__device__ __half g_SRCM[(size_t)NMAX * FD];    // mask per node (0/1)
__device__ float  g_ACCX[(size_t)NMAX * FD];    // A = xm + sum_src xm
__device__ __half g_ACCM[(size_t)NMAX * FD];    // C = mask + sum_src mask (integer counts)
__device__ float  g_DEG[NMAX];                  // 1 + in-degree
__device__ float  g_GAMMA[KMIX * NMAX];         // softmax mixture weights
__device__ float  g_INVVAR[KMIX * FD];          // exp(-logvars)
// bf16 operands for mma (linear [row][256] layouts)
__device__ __nv_bfloat16 g_Ahi[(size_t)NMAX * FD];
__device__ __nv_bfloat16 g_Alo[(size_t)NMAX * FD];
__device__ __nv_bfloat16 g_Cbf[(size_t)NMAX * FD];
// weights transposed to [o][f], hi/lo split
__device__ __nv_bfloat16 g_Whi[65536],  g_Wlo[65536];
__device__ __nv_bfloat16 g_WKhi[KMIX * 65536], g_WKlo[KMIX * 65536];
__device__ __nv_bfloat16 g_VKhi[KMIX * 65536], g_VKlo[KMIX * 65536];
__device__ int g_maskByte;
__device__ int g_edges64;

// ---------------- helpers ----------------
__device__ __forceinline__ uint32 smem_u32(const void* p) {
    uint32 a;
    asm("{ .reg .u64 t; cvta.to.shared.u64 t, %1; cvt.u32.u64 %0, t; }" : "=r"(a) : "l"(p));
    return a;
}
__device__ __forceinline__ float ex_relu(float mu, float sg) {
    if (sg <= 0.0f) return fmaxf(mu, 0.0f);
    float ss = sqrtf(sg);
    float w  = mu / ss;
    float pdf = __expf(-0.5f * w * w) * 0.3989422804014327f;
    return ss * (pdf + 0.5f * w * (1.0f + erff(w * 0.7071067811865476f)));
}
__device__ __forceinline__ void ldm4(uint32* r, uint32 a) {
    asm volatile("ldmatrix.sync.aligned.m8n8.x4.shared.b16 {%0,%1,%2,%3}, [%4];"
        : "=r"(r[0]), "=r"(r[1]), "=r"(r[2]), "=r"(r[3]) : "r"(a));
}
__device__ __forceinline__ void mma_bf16(float* d, const uint32* a, const uint32* b) {
    asm("mma.sync.aligned.m16n8k16.row.col.f32.bf16.bf16.f32 "
        "{%0,%1,%2,%3}, {%4,%5,%6,%7}, {%8,%9}, {%0,%1,%2,%3};"
        : "+f"(d[0]), "+f"(d[1]), "+f"(d[2]), "+f"(d[3])
        : "r"(a[0]), "r"(a[1]), "r"(a[2]), "r"(a[3]), "r"(b[0]), "r"(b[1]));
}

// ---------------- K0: dtype detection ----------------
__global__ void k_detect(const unsigned char* maskb, const unsigned int* edgesw) {
    __shared__ int fM, fE;
    if (threadIdx.x == 0) { fM = 0; fE = 0; }
    __syncthreads();
    int lm = 0, le = 0;
    for (int i = threadIdx.x; i < 4096; i += 256) {
        if (maskb[4 * i + 1] != 0) lm = 1;
        if (edgesw[2 * i + 1] != 0) le = 1;
    }
    if (lm) atomicOr(&fM, 1);
    if (le) atomicOr(&fE, 1);
    __syncthreads();
    if (threadIdx.x == 0) { g_maskByte = fM; g_edges64 = (fE == 0); }
}

// ---------------- K1: weight prep ([o][f] transposed, hi/lo bf16) ----------------
__global__ void k_weights(const float* __restrict__ W, const float* __restrict__ means,
                          const float* __restrict__ logvars) {
    int o = blockIdx.x;        // 0..255
    int f = threadIdx.x;       // 0..255
    int dst = o * 256 + f;
    float w = W[f * 256 + o];
    {
        __nv_bfloat16 h = __float2bfloat16_rn(w);
        g_Whi[dst] = h;
        g_Wlo[dst] = __float2bfloat16_rn(w - __bfloat162float(h));
    }
#pragma unroll
    for (int k = 0; k < KMIX; k++) {
        float wk = means[k * FD + f] * w;
        float vk = expf(logvars[k * FD + f]) * w * w;
        __nv_bfloat16 h1 = __float2bfloat16_rn(wk);
        g_WKhi[k * 65536 + dst] = h1;
        g_WKlo[k * 65536 + dst] = __float2bfloat16_rn(wk - __bfloat162float(h1));
        __nv_bfloat16 h2 = __float2bfloat16_rn(vk);
        g_VKhi[k * 65536 + dst] = h2;
        g_VKlo[k * 65536 + dst] = __float2bfloat16_rn(vk - __bfloat162float(h2));
    }
    if (o < KMIX) g_INVVAR[o * FD + f] = expf(-logvars[o * FD + f]);
}

// ---------------- K2: node init (xm, mask, gamma) ----------------
__global__ void k_init(const float* __restrict__ x, const void* __restrict__ mask,
                       const float* __restrict__ logp, const float* __restrict__ means,
                       int Nn) {
    int n = blockIdx.x;
    int f = threadIdx.x;
    int lane = f & 31, wid = f >> 5;
    size_t idx = (size_t)n * FD + f;

    int m;
    if (g_maskByte) m = ((const unsigned char*)mask)[idx] != 0;
    else            m = ((const unsigned int*)mask)[idx] != 0;

    float xv = x[idx];
    float xm = m ? 0.0f : xv;
    __half mh = __float2half((float)m);
    g_SRCX[idx] = xm;  g_ACCX[idx] = xm;
    g_SRCM[idx] = mh;  g_ACCM[idx] = mh;

    float s[KMIX];
#pragma unroll
    for (int k = 0; k < KMIX; k++) {
        float d = xv - means[k * FD + f];
        s[k] = m ? 0.0f : d * d * g_INVVAR[k * FD + f];
    }
#pragma unroll
    for (int k = 0; k < KMIX; k++)
#pragma unroll
        for (int off = 16; off; off >>= 1)
            s[k] += __shfl_down_sync(0xffffffffu, s[k], off);

    __shared__ float red[KMIX][8];
    if (lane == 0)
#pragma unroll
        for (int k = 0; k < KMIX; k++) red[k][wid] = s[k];
    __syncthreads();
    if (f == 0) {
        float li[KMIX], mx = -1e30f;
#pragma unroll
        for (int k = 0; k < KMIX; k++) {
            float S = 0.0f;
#pragma unroll
            for (int w = 0; w < 8; w++) S += red[k][w];
            li[k] = logp[k] - 0.5f * S;
            mx = fmaxf(mx, li[k]);
        }
        float se = 0.0f, ev[KMIX];
#pragma unroll
        for (int k = 0; k < KMIX; k++) { ev[k] = __expf(li[k] - mx); se += ev[k]; }
        float inv = 1.0f / se;
#pragma unroll
        for (int k = 0; k < KMIX; k++) g_GAMMA[(size_t)k * Nn + n] = ev[k] * inv;
        g_DEG[n] = 1.0f;
    }
}

// ---------------- K3: edge scatter (f32 payload + f16x2 mask counts) ----------------
__global__ void k_scatter(const void* __restrict__ edges, int E) {
    int tid = threadIdx.x;
    long long e = (long long)blockIdx.x * 4 + (tid >> 6);
    if (e >= E) return;
    int j = tid & 63;

    int s, d;
    if (g_edges64) {
        s = (int)((const long long*)edges)[e];
        d = (int)((const long long*)edges)[(size_t)E + e];
    } else {
        s = ((const int*)edges)[e];
        d = ((const int*)edges)[(size_t)E + e];
    }

    float4 v = __ldg((const float4*)(g_SRCX + (size_t)s * FD) + j);
    float* dp = g_ACCX + (size_t)d * FD + (size_t)j * 4;
    asm volatile("red.global.add.v4.f32 [%0], {%1,%2,%3,%4};"
                 :: "l"(dp), "f"(v.x), "f"(v.y), "f"(v.z), "f"(v.w) : "memory");

    const __half2* ms = (const __half2*)(g_SRCM + (size_t)s * FD);
    __half2* md = (__half2*)(g_ACCM + (size_t)d * FD);
    __half2 m0 = __ldg(ms + j);
    __half2 m1 = __ldg(ms + 64 + j);
    atomicAdd(md + j, m0);
    atomicAdd(md + 64 + j, m1);

    if (j == 0) atomicAdd(&g_DEG[d], 1.0f);
}

// ---------------- K3b: convert accumulators to bf16 hi/lo ----------------
__global__ void k_conv(int total4) {
    int i = blockIdx.x * 256 + threadIdx.x;
    if (i >= total4) return;
    size_t b = (size_t)i * 4;
    float4 v = *(const float4*)&g_ACCX[b];
    float vv[4] = { v.x, v.y, v.z, v.w };
    __nv_bfloat16 hi[4], lo[4];
#pragma unroll
    for (int j = 0; j < 4; j++) {
        hi[j] = __float2bfloat16_rn(vv[j]);
        lo[j] = __float2bfloat16_rn(vv[j] - __bfloat162float(hi[j]));
    }
    *(__nv_bfloat162*)&g_Ahi[b]     = __halves2bfloat162(hi[0], hi[1]);
    *(__nv_bfloat162*)&g_Ahi[b + 2] = __halves2bfloat162(hi[2], hi[3]);
    *(__nv_bfloat162*)&g_Alo[b]     = __halves2bfloat162(lo[0], lo[1]);
    *(__nv_bfloat162*)&g_Alo[b + 2] = __halves2bfloat162(lo[2], lo[3]);
    __half2 c0 = *(const __half2*)&g_ACCM[b];
    __half2 c1 = *(const __half2*)&g_ACCM[b + 2];
    float2 f0 = __half22float2(c0), f1 = __half22float2(c1);
    *(__nv_bfloat162*)&g_Cbf[b] =
        __halves2bfloat162(__float2bfloat16_rn(f0.x), __float2bfloat16_rn(f0.y));
    *(__nv_bfloat162*)&g_Cbf[b + 2] =
        __halves2bfloat162(__float2bfloat16_rn(f1.x), __float2bfloat16_rn(f1.y));
}

// ---------------- K4: mma.sync fused GEMM + ex_relu + mixture ----------------
// SMEM: [0, 64K) C tiles (4 x 16KB, swizzled 128x64 bf16)
//       [64K, 64K+48K) arena:
//         phase A: Ahi(16K) Alo(16K) Whi(8K) Wlo(8K)
//         phase B: WKhi(8K) WKlo(8K) VKhi(8K) VKlo(8K)
#define SM_AR    65536
#define SM_TOTAL (65536 + 49152)

__device__ __forceinline__ void cp128(char* dst, const __nv_bfloat16* src,
                                      int node0, int Nn, int kc, int tid) {
#pragma unroll
    for (int i = 0; i < 4; i++) {
        int p = tid + i * 256;
        int r = p >> 3, s = p & 7;
        int gn = node0 + r; if (gn >= Nn) gn = Nn - 1;
        uint4 v = *(const uint4*)(src + (size_t)gn * 256 + kc * 64 + s * 8);
        *(uint4*)(dst + r * 128 + ((s * 16) ^ ((r & 7) << 4))) = v;
    }
}
__device__ __forceinline__ void cp64(char* dst, const __nv_bfloat16* src, int tid) {
#pragma unroll
    for (int i = 0; i < 2; i++) {
        int p = tid + i * 256;
        int r = p >> 3, s = p & 7;
        uint4 v = *(const uint4*)(src + (size_t)r * 256 + s * 8);
        *(uint4*)(dst + r * 128 + ((s * 16) ^ ((r & 7) << 4))) = v;
    }
}

__global__ void __launch_bounds__(256, 1)
k_gemm(const float* __restrict__ bias, float* __restrict__ out, int Nn) {
    extern __shared__ char sm[];
    uint32 sbase = smem_u32(sm);
    int tid = threadIdx.x, lane = tid & 31, w = tid >> 5;
    int mb = (w & 3) * 32;          // warp M rows within 128-tile
    int cg = w >> 2;                // warp N group (0/1): cols cg*32..+32
    int node0 = blockIdx.x * 128;
    int bo = blockIdx.y * 64;       // output col base

    // ldmatrix offsets: A/C tiles (128 rows)
    int aoff[2][4];
#pragma unroll
    for (int mt = 0; mt < 2; mt++) {
        int r = mb + mt * 16 + (lane & 15);
        int kseg = lane >> 4;
#pragma unroll
        for (int ks = 0; ks < 4; ks++)
            aoff[mt][ks] = r * 128 + ((kseg * 16 + ks * 32) ^ ((r & 7) << 4));
    }
    // weight tiles (64 rows): pair p covers n8-tiles 2p, 2p+1
    int woff[2][4];
#pragma unroll
    for (int p = 0; p < 2; p++) {
        int r = cg * 32 + (p * 2 + (lane >> 4)) * 8 + (lane & 7);
        int kseg = (lane >> 3) & 1;
#pragma unroll
        for (int ks = 0; ks < 4; ks++)
            woff[p][ks] = r * 128 + ((kseg * 16 + ks * 32) ^ ((r & 7) << 4));
    }

    // preload C tiles (used in phase B)
#pragma unroll
    for (int kc = 0; kc < 4; kc++)
        cp128(sm + kc * 16384, g_Cbf, node0, Nn, kc, tid);

    float P[2][4][4];
#pragma unroll
    for (int mt = 0; mt < 2; mt++)
#pragma unroll
        for (int nt = 0; nt < 4; nt++)
#pragma unroll
            for (int rr = 0; rr < 4; rr++) P[mt][nt][rr] = 0.0f;

    char* AR = sm + SM_AR;
    uint32 sAh = sbase + SM_AR, sAl = sAh + 16384, sWh = sAl + 16384, sWl = sWh + 8192;

    // ---- phase A: P = A @ W (3-pass hi/lo) ----
    for (int kc = 0; kc < 4; kc++) {
        __syncthreads();
        cp128(AR, g_Ahi, node0, Nn, kc, tid);
        cp128(AR + 16384, g_Alo, node0, Nn, kc, tid);
        cp64(AR + 32768, g_Whi + bo * 256 + kc * 64, tid);
        cp64(AR + 40960, g_Wlo + bo * 256 + kc * 64, tid);
        __syncthreads();
#pragma unroll
        for (int ks = 0; ks < 4; ks++) {
            uint32 ah[2][4], al[2][4], wh[2][4], wl[2][4];
            ldm4(ah[0], sAh + aoff[0][ks]); ldm4(ah[1], sAh + aoff[1][ks]);
            ldm4(al[0], sAl + aoff[0][ks]); ldm4(al[1], sAl + aoff[1][ks]);
            ldm4(wh[0], sWh + woff[0][ks]); ldm4(wh[1], sWh + woff[1][ks]);
            ldm4(wl[0], sWl + woff[0][ks]); ldm4(wl[1], sWl + woff[1][ks]);
#pragma unroll
            for (int mt = 0; mt < 2; mt++)
#pragma unroll
                for (int nt = 0; nt < 4; nt++) {
                    const uint32* bh = &wh[nt >> 1][(nt & 1) * 2];
                    const uint32* bl = &wl[nt >> 1][(nt & 1) * 2];
                    mma_bf16(P[mt][nt], ah[mt], bh);
                    mma_bf16(P[mt][nt], al[mt], bh);
                    mma_bf16(P[mt][nt], ah[mt], bl);
                }
        }
    }

    // fold deg*bias into P; gather per-row constants
    int mrow[2][2];
    float degv[2][2];
#pragma unroll
    for (int mt = 0; mt < 2; mt++)
#pragma unroll
        for (int h = 0; h < 2; h++) {
            int m = node0 + mb + mt * 16 + (lane >> 2) + 8 * h;
            mrow[mt][h] = m < Nn ? m : Nn - 1;
            degv[mt][h] = g_DEG[mrow[mt][h]];
        }
    float bv[4][2];
#pragma unroll
    for (int nt = 0; nt < 4; nt++)
#pragma unroll
        for (int c = 0; c < 2; c++)
            bv[nt][c] = __ldg(&bias[bo + cg * 32 + nt * 8 + 2 * (lane & 3) + c]);
#pragma unroll
    for (int mt = 0; mt < 2; mt++)
#pragma unroll
        for (int nt = 0; nt < 4; nt++)
#pragma unroll
            for (int rr = 0; rr < 4; rr++)
                P[mt][nt][rr] += degv[mt][rr >> 1] * bv[nt][rr & 1];

    float OA[2][4][4];
#pragma unroll
    for (int mt = 0; mt < 2; mt++)
#pragma unroll
        for (int nt = 0; nt < 4; nt++)
#pragma unroll
            for (int rr = 0; rr < 4; rr++) OA[mt][nt][rr] = 0.0f;

    // ---- phase B: per-k Q = C@WK, S = C@VK (2-pass each) + fused epilogue ----
    uint32 sW0 = sbase + SM_AR, sW1 = sW0 + 8192, sV0 = sW1 + 8192, sV1 = sV0 + 8192;
    for (int k = 0; k < KMIX; k++) {
        float Q[2][4][4], S[2][4][4];
#pragma unroll
        for (int mt = 0; mt < 2; mt++)
#pragma unroll
            for (int nt = 0; nt < 4; nt++)
#pragma unroll
                for (int rr = 0; rr < 4; rr++) { Q[mt][nt][rr] = 0.0f; S[mt][nt][rr] = 0.0f; }

        for (int kc = 0; kc < 4; kc++) {
            __syncthreads();
            size_t wb = (size_t)k * 65536 + bo * 256 + kc * 64;
            cp64(AR,         g_WKhi + wb, tid);
            cp64(AR + 8192,  g_WKlo + wb, tid);
            cp64(AR + 16384, g_VKhi + wb, tid);
            cp64(AR + 24576, g_VKlo + wb, tid);
            __syncthreads();
            uint32 sC = sbase + kc * 16384;
#pragma unroll
            for (int ks = 0; ks < 4; ks++) {
                uint32 cf[2][4], kwh[2][4], kwl[2][4], kvh[2][4], kvl[2][4];
                ldm4(cf[0], sC + aoff[0][ks]); ldm4(cf[1], sC + aoff[1][ks]);
                ldm4(kwh[0], sW0 + woff[0][ks]); ldm4(kwh[1], sW0 + woff[1][ks]);
                ldm4(kwl[0], sW1 + woff[0][ks]); ldm4(kwl[1], sW1 + woff[1][ks]);
                ldm4(kvh[0], sV0 + woff[0][ks]); ldm4(kvh[1], sV0 + woff[1][ks]);
                ldm4(kvl[0], sV1 + woff[0][ks]); ldm4(kvl[1], sV1 + woff[1][ks]);
#pragma unroll
                for (int mt = 0; mt < 2; mt++)
#pragma unroll
                    for (int nt = 0; nt < 4; nt++) {
                        const uint32* wh2 = &kwh[nt >> 1][(nt & 1) * 2];
                        const uint32* wl2 = &kwl[nt >> 1][(nt & 1) * 2];
                        const uint32* vh2 = &kvh[nt >> 1][(nt & 1) * 2];
                        const uint32* vl2 = &kvl[nt >> 1][(nt & 1) * 2];
                        mma_bf16(Q[mt][nt], cf[mt], wh2);
                        mma_bf16(Q[mt][nt], cf[mt], wl2);
                        mma_bf16(S[mt][nt], cf[mt], vh2);
                        mma_bf16(S[mt][nt], cf[mt], vl2);
                    }
            }
        }
        // epilogue for this k
        float gam[2][2];
#pragma unroll
        for (int mt = 0; mt < 2; mt++)
#pragma unroll
            for (int h = 0; h < 2; h++)
                gam[mt][h] = g_GAMMA[(size_t)k * Nn + mrow[mt][h]];
#pragma unroll
        for (int mt = 0; mt < 2; mt++)
#pragma unroll
            for (int nt = 0; nt < 4; nt++)
#pragma unroll
                for (int rr = 0; rr < 4; rr++) {
                    float mu = P[mt][nt][rr] + Q[mt][nt][rr];
                    float sg = fmaxf(S[mt][nt][rr], 0.0f);
                    OA[mt][nt][rr] += gam[mt][rr >> 1] * ex_relu(mu, sg);
                }
    }

    // ---- store (float2 per (mt,nt,h)) ----
#pragma unroll
    for (int mt = 0; mt < 2; mt++)
#pragma unroll
        for (int h = 0; h < 2; h++) {
            int m = node0 + mb + mt * 16 + (lane >> 2) + 8 * h;
            if (m < Nn) {
                float* op = out + (size_t)m * 256 + bo + cg * 32 + 2 * (lane & 3);
#pragma unroll
                for (int nt = 0; nt < 4; nt++)
                    *(float2*)(op + nt * 8) =
                        make_float2(OA[mt][nt][2 * h], OA[mt][nt][2 * h + 1]);
            }
        }
}

// ---------------- launch ----------------
extern "C" void kernel_launch(void* const* d_in, const int* in_sizes, int n_in,
                              void* d_out, int out_size) {
    const float* x       = (const float*)d_in[0];
    const void*  edges   = (const void*) d_in[1];
    const void*  mask    = (const void*) d_in[2];
    const float* logp    = (const float*)d_in[3];
    const float* means   = (const float*)d_in[4];
    const float* logvars = (const float*)d_in[5];
    const float* W       = (const float*)d_in[6];
    const float* bias    = (const float*)d_in[7];
    float* out = (float*)d_out;

    int Nn = in_sizes[0] / FD;      // 50000
    int E  = in_sizes[1] / 2;       // 1600000

    k_detect<<<1, 256>>>((const unsigned char*)mask, (const unsigned int*)edges);
    k_weights<<<FD, FD>>>(W, means, logvars);
    k_init<<<Nn, 256>>>(x, mask, logp, means, Nn);
    k_scatter<<<(E + 3) / 4, 256>>>(edges, E);
    int total4 = Nn * 64;
    k_conv<<<(total4 + 255) / 256, 256>>>(total4);

    static int attr_set = 0;
    if (!attr_set) {
        cudaFuncSetAttribute(k_gemm, cudaFuncAttributeMaxDynamicSharedMemorySize, SM_TOTAL);
        attr_set = 1;
    }
    dim3 grid((Nn + 127) / 128, 4);
    k_gemm<<<grid, 256, SM_TOTAL>>>(bias, out, Nn);
}

// round 8
// speedup vs baseline: 2.8968x; 1.6226x over previous
#include <cuda_runtime.h>
#include <cuda_bf16.h>
#include <cuda_fp16.h>
#include <math.h>
#include <stdint.h>

typedef unsigned int uint32;
typedef unsigned long long ull;

#define NMAX 50000
#define EMAX 1700000
#define FD   256
#define KMIX 5

// ---------------- scratch (allocation-free: __device__ globals) ----------------
__device__ float  g_SRCX[(size_t)NMAX * FD];    // masked x (xm) per node
__device__ __half g_SRCM[(size_t)NMAX * FD];    // mask per node (0/1)
__device__ float  g_DEG[NMAX];                  // 1 + in-degree
__device__ float  g_GAMMA[KMIX * NMAX];         // softmax mixture weights
__device__ float  g_INVVAR[KMIX * FD];          // exp(-logvars)
// bf16 operands for mma (linear [row][256] layouts)
__device__ __nv_bfloat16 g_Ahi[(size_t)NMAX * FD];
__device__ __nv_bfloat16 g_Alo[(size_t)NMAX * FD];
__device__ __nv_bfloat16 g_Cbf[(size_t)NMAX * FD];
// weights transposed to [o][f], hi/lo split
__device__ __nv_bfloat16 g_Whi[65536],  g_Wlo[65536];
__device__ __nv_bfloat16 g_WKhi[KMIX * 65536], g_WKlo[KMIX * 65536];
__device__ __nv_bfloat16 g_VKhi[KMIX * 65536], g_VKlo[KMIX * 65536];
// CSR by dst
__device__ int g_cnt[NMAX];
__device__ int g_loc[NMAX];
__device__ int g_bsum[64];
__device__ int g_rowptr[NMAX + 1];
__device__ int g_wptr[NMAX];
__device__ int g_srclist[EMAX];
__device__ int g_maskByte;
__device__ int g_edges64;

// ---------------- helpers ----------------
__device__ __forceinline__ uint32 smem_u32(const void* p) {
    uint32 a;
    asm("{ .reg .u64 t; cvta.to.shared.u64 t, %1; cvt.u32.u64 %0, t; }" : "=r"(a) : "l"(p));
    return a;
}
__device__ __forceinline__ float ex_relu(float mu, float sg) {
    if (sg <= 0.0f) return fmaxf(mu, 0.0f);
    float ss = sqrtf(sg);
    float w  = mu / ss;
    float pdf = __expf(-0.5f * w * w) * 0.3989422804014327f;
    return ss * (pdf + 0.5f * w * (1.0f + erff(w * 0.7071067811865476f)));
}
__device__ __forceinline__ void ldm4(uint32* r, uint32 a) {
    asm volatile("ldmatrix.sync.aligned.m8n8.x4.shared.b16 {%0,%1,%2,%3}, [%4];"
        : "=r"(r[0]), "=r"(r[1]), "=r"(r[2]), "=r"(r[3]) : "r"(a));
}
__device__ __forceinline__ void mma_bf16(float* d, const uint32* a, const uint32* b) {
    asm("mma.sync.aligned.m16n8k16.row.col.f32.bf16.bf16.f32 "
        "{%0,%1,%2,%3}, {%4,%5,%6,%7}, {%8,%9}, {%0,%1,%2,%3};"
        : "+f"(d[0]), "+f"(d[1]), "+f"(d[2]), "+f"(d[3])
        : "r"(a[0]), "r"(a[1]), "r"(a[2]), "r"(a[3]), "r"(b[0]), "r"(b[1]));
}
#define CPA16(dst, src) \
    asm volatile("cp.async.ca.shared.global [%0], [%1], 16;" :: "r"(dst), "l"(src))
#define CPA_COMMIT() asm volatile("cp.async.commit_group;")
#define CPA_WAIT(n)  asm volatile("cp.async.wait_group %0;" :: "n"(n))

// ---------------- K0: dtype detection ----------------
__global__ void k_detect(const unsigned char* maskb, const unsigned int* edgesw) {
    __shared__ int fM, fE;
    if (threadIdx.x == 0) { fM = 0; fE = 0; }
    __syncthreads();
    int lm = 0, le = 0;
    for (int i = threadIdx.x; i < 4096; i += 256) {
        if (maskb[4 * i + 1] != 0) lm = 1;
        if (edgesw[2 * i + 1] != 0) le = 1;
    }
    if (lm) atomicOr(&fM, 1);
    if (le) atomicOr(&fE, 1);
    __syncthreads();
    if (threadIdx.x == 0) { g_maskByte = fM; g_edges64 = (fE == 0); }
}

__global__ void k_zero(int Nn) {
    int i = blockIdx.x * 256 + threadIdx.x;
    if (i < Nn) g_cnt[i] = 0;
}

// ---------------- K1: weight prep ([o][f] transposed, hi/lo bf16) ----------------
__global__ void k_weights(const float* __restrict__ W, const float* __restrict__ means,
                          const float* __restrict__ logvars) {
    int o = blockIdx.x;
    int f = threadIdx.x;
    int dst = o * 256 + f;
    float w = W[f * 256 + o];
    {
        __nv_bfloat16 h = __float2bfloat16_rn(w);
        g_Whi[dst] = h;
        g_Wlo[dst] = __float2bfloat16_rn(w - __bfloat162float(h));
    }
#pragma unroll
    for (int k = 0; k < KMIX; k++) {
        float wk = means[k * FD + f] * w;
        float vk = expf(logvars[k * FD + f]) * w * w;
        __nv_bfloat16 h1 = __float2bfloat16_rn(wk);
        g_WKhi[k * 65536 + dst] = h1;
        g_WKlo[k * 65536 + dst] = __float2bfloat16_rn(wk - __bfloat162float(h1));
        __nv_bfloat16 h2 = __float2bfloat16_rn(vk);
        g_VKhi[k * 65536 + dst] = h2;
        g_VKlo[k * 65536 + dst] = __float2bfloat16_rn(vk - __bfloat162float(h2));
    }
    if (o < KMIX) g_INVVAR[o * FD + f] = expf(-logvars[o * FD + f]);
}

// ---------------- K2: node init (xm, mask, gamma) ----------------
__global__ void k_init(const float* __restrict__ x, const void* __restrict__ mask,
                       const float* __restrict__ logp, const float* __restrict__ means,
                       int Nn) {
    int n = blockIdx.x;
    int f = threadIdx.x;
    int lane = f & 31, wid = f >> 5;
    size_t idx = (size_t)n * FD + f;

    int m;
    if (g_maskByte) m = ((const unsigned char*)mask)[idx] != 0;
    else            m = ((const unsigned int*)mask)[idx] != 0;

    float xv = x[idx];
    float xm = m ? 0.0f : xv;
    g_SRCX[idx] = xm;
    g_SRCM[idx] = __float2half((float)m);

    float s[KMIX];
#pragma unroll
    for (int k = 0; k < KMIX; k++) {
        float d = xv - means[k * FD + f];
        s[k] = m ? 0.0f : d * d * g_INVVAR[k * FD + f];
    }
#pragma unroll
    for (int k = 0; k < KMIX; k++)
#pragma unroll
        for (int off = 16; off; off >>= 1)
            s[k] += __shfl_down_sync(0xffffffffu, s[k], off);

    __shared__ float red[KMIX][8];
    if (lane == 0)
#pragma unroll
        for (int k = 0; k < KMIX; k++) red[k][wid] = s[k];
    __syncthreads();
    if (f == 0) {
        float li[KMIX], mx = -1e30f;
#pragma unroll
        for (int k = 0; k < KMIX; k++) {
            float S = 0.0f;
#pragma unroll
            for (int w = 0; w < 8; w++) S += red[k][w];
            li[k] = logp[k] - 0.5f * S;
            mx = fmaxf(mx, li[k]);
        }
        float se = 0.0f, ev[KMIX];
#pragma unroll
        for (int k = 0; k < KMIX; k++) { ev[k] = __expf(li[k] - mx); se += ev[k]; }
        float inv = 1.0f / se;
#pragma unroll
        for (int k = 0; k < KMIX; k++) g_GAMMA[(size_t)k * Nn + n] = ev[k] * inv;
    }
}

// ---------------- CSR build ----------------
__global__ void k_hist(const void* __restrict__ edges, int E) {
    int stride = gridDim.x * 256;
    for (int i = blockIdx.x * 256 + threadIdx.x; i < E; i += stride) {
        int d = g_edges64 ? (int)((const long long*)edges)[(size_t)E + i]
                          : ((const int*)edges)[(size_t)E + i];
        atomicAdd(&g_cnt[d], 1);
    }
}
__global__ void k_s1(int Nn) {
    __shared__ int sc[1024];
    int t = threadIdx.x;
    int idx = blockIdx.x * 1024 + t;
    int v = idx < Nn ? g_cnt[idx] : 0;
    sc[t] = v;
    __syncthreads();
    for (int off = 1; off < 1024; off <<= 1) {
        int u = (t >= off) ? sc[t - off] : 0;
        __syncthreads();
        sc[t] += u;
        __syncthreads();
    }
    if (idx < Nn) g_loc[idx] = sc[t] - v;
    if (t == 1023) g_bsum[blockIdx.x] = sc[1023];
}
__global__ void k_s2(int nb) {
    if (threadIdx.x == 0) {
        int run = 0;
        for (int i = 0; i < nb; i++) { int v = g_bsum[i]; g_bsum[i] = run; run += v; }
    }
}
__global__ void k_s3(int Nn, int E) {
    int idx = blockIdx.x * 1024 + threadIdx.x;
    if (idx < Nn) {
        int r = g_loc[idx] + g_bsum[idx >> 10];
        g_rowptr[idx] = r;
        g_wptr[idx] = r;
    }
    if (idx == 0) g_rowptr[Nn] = E;
}
__global__ void k_fill(const void* __restrict__ edges, int E) {
    int stride = gridDim.x * 256;
    for (int i = blockIdx.x * 256 + threadIdx.x; i < E; i += stride) {
        int s, d;
        if (g_edges64) {
            s = (int)((const long long*)edges)[i];
            d = (int)((const long long*)edges)[(size_t)E + i];
        } else {
            s = ((const int*)edges)[i];
            d = ((const int*)edges)[(size_t)E + i];
        }
        int slot = atomicAdd(&g_wptr[d], 1);
        g_srclist[slot] = s;
    }
}

// ---------------- K3: gather (register accumulation, emits bf16 hi/lo + Cbf) ----------------
__device__ __forceinline__ void acc_src(int s, int lane, float& ax, float& ay, float& az,
                                        float& aw, float& m0, float& m1, float& m2, float& m3) {
    float4 v = __ldg((const float4*)g_SRCX + (size_t)s * 64 + lane);
    uint2 u = __ldg((const uint2*)(g_SRCM + (size_t)s * 256) + lane);
    float2 c0 = __half22float2(*(__half2*)&u.x);
    float2 c1 = __half22float2(*(__half2*)&u.y);
    ax += v.x; ay += v.y; az += v.z; aw += v.w;
    m0 += c0.x; m1 += c0.y; m2 += c1.x; m3 += c1.y;
}
__global__ void __launch_bounds__(256)
k_gather(int Nn) {
    int tid = threadIdx.x;
    int lane = tid & 63, grp = tid >> 6;
    int G = gridDim.x * 4;
    for (int d = blockIdx.x * 4 + grp; d < Nn; d += G) {
        int beg = g_rowptr[d], end = g_rowptr[d + 1];
        float4 a = __ldg((const float4*)g_SRCX + (size_t)d * 64 + lane);
        uint2 mu = __ldg((const uint2*)(g_SRCM + (size_t)d * 256) + lane);
        float2 c0 = __half22float2(*(__half2*)&mu.x);
        float2 c1 = __half22float2(*(__half2*)&mu.y);
        float ax = a.x, ay = a.y, az = a.z, aw = a.w;
        float m0 = c0.x, m1 = c0.y, m2 = c1.x, m3 = c1.y;
        int e = beg;
        for (; e + 4 <= end; e += 4) {
            int s0 = __ldg(&g_srclist[e]);
            int s1 = __ldg(&g_srclist[e + 1]);
            int s2 = __ldg(&g_srclist[e + 2]);
            int s3 = __ldg(&g_srclist[e + 3]);
            acc_src(s0, lane, ax, ay, az, aw, m0, m1, m2, m3);
            acc_src(s1, lane, ax, ay, az, aw, m0, m1, m2, m3);
            acc_src(s2, lane, ax, ay, az, aw, m0, m1, m2, m3);
            acc_src(s3, lane, ax, ay, az, aw, m0, m1, m2, m3);
        }
        for (; e < end; e++)
            acc_src(__ldg(&g_srclist[e]), lane, ax, ay, az, aw, m0, m1, m2, m3);

        size_t ob = (size_t)d * 256 + lane * 4;
        float vv[4] = { ax, ay, az, aw };
        __nv_bfloat16 hi[4], lo[4];
#pragma unroll
        for (int j = 0; j < 4; j++) {
            hi[j] = __float2bfloat16_rn(vv[j]);
            lo[j] = __float2bfloat16_rn(vv[j] - __bfloat162float(hi[j]));
        }
        *(__nv_bfloat162*)&g_Ahi[ob]     = __halves2bfloat162(hi[0], hi[1]);
        *(__nv_bfloat162*)&g_Ahi[ob + 2] = __halves2bfloat162(hi[2], hi[3]);
        *(__nv_bfloat162*)&g_Alo[ob]     = __halves2bfloat162(lo[0], lo[1]);
        *(__nv_bfloat162*)&g_Alo[ob + 2] = __halves2bfloat162(lo[2], lo[3]);
        *(__nv_bfloat162*)&g_Cbf[ob] =
            __halves2bfloat162(__float2bfloat16_rn(m0), __float2bfloat16_rn(m1));
        *(__nv_bfloat162*)&g_Cbf[ob + 2] =
            __halves2bfloat162(__float2bfloat16_rn(m2), __float2bfloat16_rn(m3));
        if (lane == 0) g_DEG[d] = 1.0f + (float)(end - beg);
    }
}

// ---------------- K4: mma.sync fused GEMM, cp.async double-buffered ----------------
// SMEM: [0, 64K) C tiles (4 x 16KB swizzled) ; [64K, 64K+96K) double-buffered arena.
#define STG_A 49152
#define SM_AR 65536
#define SM_TOTAL (65536 + 2 * 49152)

__device__ __forceinline__ void cpa128(uint32 dstb, const __nv_bfloat16* src,
                                       int node0, int Nn, int kc, int tid) {
#pragma unroll
    for (int i = 0; i < 4; i++) {
        int p = tid + i * 256;
        int r = p >> 3, s = p & 7;
        int gn = node0 + r; if (gn >= Nn) gn = Nn - 1;
        const void* g = src + (size_t)gn * 256 + kc * 64 + s * 8;
        CPA16(dstb + r * 128 + ((s * 16) ^ ((r & 7) << 4)), g);
    }
}
__device__ __forceinline__ void cpa64(uint32 dstb, const __nv_bfloat16* src, int tid) {
#pragma unroll
    for (int i = 0; i < 2; i++) {
        int p = tid + i * 256;
        int r = p >> 3, s = p & 7;
        const void* g = src + (size_t)r * 256 + s * 8;
        CPA16(dstb + r * 128 + ((s * 16) ^ ((r & 7) << 4)), g);
    }
}

__global__ void __launch_bounds__(256, 1)
k_gemm(const float* __restrict__ bias, float* __restrict__ out, int Nn) {
    extern __shared__ char sm[];
    uint32 sbase = smem_u32(sm);
    int tid = threadIdx.x, lane = tid & 31, w = tid >> 5;
    int mb = (w & 3) * 32;
    int cg = w >> 2;
    int node0 = blockIdx.x * 128;
    int bo = blockIdx.y * 64;
    uint32 sAR = sbase + SM_AR;

    // ldmatrix offsets (relative to tile base)
    int aoff[2][4];
#pragma unroll
    for (int mt = 0; mt < 2; mt++) {
        int r = mb + mt * 16 + (lane & 15);
        int kseg = lane >> 4;
#pragma unroll
        for (int ks = 0; ks < 4; ks++)
            aoff[mt][ks] = r * 128 + ((kseg * 16 + ks * 32) ^ ((r & 7) << 4));
    }
    int woff[2][4];
#pragma unroll
    for (int p = 0; p < 2; p++) {
        int r = cg * 32 + (p * 2 + (lane >> 4)) * 8 + (lane & 7);
        int kseg = (lane >> 3) & 1;
#pragma unroll
        for (int ks = 0; ks < 4; ks++)
            woff[p][ks] = r * 128 + ((kseg * 16 + ks * 32) ^ ((r & 7) << 4));
    }

    // async preload C tiles (group 0)
#pragma unroll
    for (int kc = 0; kc < 4; kc++)
        cpa128(sbase + kc * 16384, g_Cbf, node0, Nn, kc, tid);
    CPA_COMMIT();

    auto issueA = [&](int kc) {
        uint32 b = sAR + (kc & 1) * STG_A;
        cpa128(b,         g_Ahi, node0, Nn, kc, tid);
        cpa128(b + 16384, g_Alo, node0, Nn, kc, tid);
        cpa64(b + 32768, g_Whi + bo * 256 + kc * 64, tid);
        cpa64(b + 40960, g_Wlo + bo * 256 + kc * 64, tid);
        CPA_COMMIT();
    };
    auto issueB = [&](int t) {
        int k = t >> 2, kc = t & 3;
        uint32 b = sAR + (t & 1) * 32768;
        size_t wb = (size_t)k * 65536 + bo * 256 + kc * 64;
        cpa64(b,         g_WKhi + wb, tid);
        cpa64(b + 8192,  g_WKlo + wb, tid);
        cpa64(b + 16384, g_VKhi + wb, tid);
        cpa64(b + 24576, g_VKlo + wb, tid);
        CPA_COMMIT();
    };

    float P[2][4][4];
#pragma unroll
    for (int mt = 0; mt < 2; mt++)
#pragma unroll
        for (int nt = 0; nt < 4; nt++)
#pragma unroll
            for (int rr = 0; rr < 4; rr++) P[mt][nt][rr] = 0.0f;

    // ---- phase A: P = A @ W (3-pass hi/lo), 2-stage pipeline ----
    issueA(0);
    for (int kc = 0; kc < 4; kc++) {
        if (kc < 3) issueA(kc + 1); else issueB(0);
        CPA_WAIT(1);
        __syncthreads();
        uint32 bA = sAR + (kc & 1) * STG_A;
        uint32 sAh = bA, sAl = bA + 16384, sWh = bA + 32768, sWl = bA + 40960;
#pragma unroll
        for (int ks = 0; ks < 4; ks++) {
            uint32 ah[2][4], al[2][4], wh[2][4], wl[2][4];
            ldm4(ah[0], sAh + aoff[0][ks]); ldm4(ah[1], sAh + aoff[1][ks]);
            ldm4(al[0], sAl + aoff[0][ks]); ldm4(al[1], sAl + aoff[1][ks]);
            ldm4(wh[0], sWh + woff[0][ks]); ldm4(wh[1], sWh + woff[1][ks]);
            ldm4(wl[0], sWl + woff[0][ks]); ldm4(wl[1], sWl + woff[1][ks]);
#pragma unroll
            for (int mt = 0; mt < 2; mt++)
#pragma unroll
                for (int nt = 0; nt < 4; nt++) {
                    const uint32* bh = &wh[nt >> 1][(nt & 1) * 2];
                    const uint32* bl = &wl[nt >> 1][(nt & 1) * 2];
                    mma_bf16(P[mt][nt], ah[mt], bh);
                    mma_bf16(P[mt][nt], al[mt], bh);
                    mma_bf16(P[mt][nt], ah[mt], bl);
                }
        }
        __syncthreads();
    }

    // fold deg*bias into P
    int mrow[2][2];
    float degv[2][2];
#pragma unroll
    for (int mt = 0; mt < 2; mt++)
#pragma unroll
        for (int h = 0; h < 2; h++) {
            int m = node0 + mb + mt * 16 + (lane >> 2) + 8 * h;
            mrow[mt][h] = m < Nn ? m : Nn - 1;
            degv[mt][h] = g_DEG[mrow[mt][h]];
        }
    float bv[4][2];
#pragma unroll
    for (int nt = 0; nt < 4; nt++)
#pragma unroll
        for (int c = 0; c < 2; c++)
            bv[nt][c] = __ldg(&bias[bo + cg * 32 + nt * 8 + 2 * (lane & 3) + c]);
#pragma unroll
    for (int mt = 0; mt < 2; mt++)
#pragma unroll
        for (int nt = 0; nt < 4; nt++)
#pragma unroll
            for (int rr = 0; rr < 4; rr++)
                P[mt][nt][rr] += degv[mt][rr >> 1] * bv[nt][rr & 1];

    float OA[2][4][4];
#pragma unroll
    for (int mt = 0; mt < 2; mt++)
#pragma unroll
        for (int nt = 0; nt < 4; nt++)
#pragma unroll
            for (int rr = 0; rr < 4; rr++) OA[mt][nt][rr] = 0.0f;

    // ---- phase B: 20 stages (k,kc), 2-stage pipeline ----
    float Q[2][4][4], S[2][4][4];
    for (int t = 0; t < 20; t++) {
        int k = t >> 2, kc = t & 3;
        if (t < 19) issueB(t + 1);
        if (t < 19) CPA_WAIT(1); else CPA_WAIT(0);
        __syncthreads();
        if (kc == 0) {
#pragma unroll
            for (int mt = 0; mt < 2; mt++)
#pragma unroll
                for (int nt = 0; nt < 4; nt++)
#pragma unroll
                    for (int rr = 0; rr < 4; rr++) { Q[mt][nt][rr] = 0.0f; S[mt][nt][rr] = 0.0f; }
        }
        uint32 bB = sAR + (t & 1) * 32768;
        uint32 sW0 = bB, sW1 = bB + 8192, sV0 = bB + 16384, sV1 = bB + 24576;
        uint32 sC = sbase + kc * 16384;
#pragma unroll
        for (int ks = 0; ks < 4; ks++) {
            uint32 cf[2][4], kwh[2][4], kwl[2][4], kvh[2][4], kvl[2][4];
            ldm4(cf[0], sC + aoff[0][ks]); ldm4(cf[1], sC + aoff[1][ks]);
            ldm4(kwh[0], sW0 + woff[0][ks]); ldm4(kwh[1], sW0 + woff[1][ks]);
            ldm4(kwl[0], sW1 + woff[0][ks]); ldm4(kwl[1], sW1 + woff[1][ks]);
            ldm4(kvh[0], sV0 + woff[0][ks]); ldm4(kvh[1], sV0 + woff[1][ks]);
            ldm4(kvl[0], sV1 + woff[0][ks]); ldm4(kvl[1], sV1 + woff[1][ks]);
#pragma unroll
            for (int mt = 0; mt < 2; mt++)
#pragma unroll
                for (int nt = 0; nt < 4; nt++) {
                    const uint32* wh2 = &kwh[nt >> 1][(nt & 1) * 2];
                    const uint32* wl2 = &kwl[nt >> 1][(nt & 1) * 2];
                    const uint32* vh2 = &kvh[nt >> 1][(nt & 1) * 2];
                    const uint32* vl2 = &kvl[nt >> 1][(nt & 1) * 2];
                    mma_bf16(Q[mt][nt], cf[mt], wh2);
                    mma_bf16(Q[mt][nt], cf[mt], wl2);
                    mma_bf16(S[mt][nt], cf[mt], vh2);
                    mma_bf16(S[mt][nt], cf[mt], vl2);
                }
        }
        if (kc == 3) {
            float gam[2][2];
#pragma unroll
            for (int mt = 0; mt < 2; mt++)
#pragma unroll
                for (int h = 0; h < 2; h++)
                    gam[mt][h] = g_GAMMA[(size_t)k * Nn + mrow[mt][h]];
#pragma unroll
            for (int mt = 0; mt < 2; mt++)
#pragma unroll
                for (int nt = 0; nt < 4; nt++)
#pragma unroll
                    for (int rr = 0; rr < 4; rr++) {
                        float mu = P[mt][nt][rr] + Q[mt][nt][rr];
                        float sg = fmaxf(S[mt][nt][rr], 0.0f);
                        OA[mt][nt][rr] += gam[mt][rr >> 1] * ex_relu(mu, sg);
                    }
        }
        __syncthreads();
    }

    // ---- store ----
#pragma unroll
    for (int mt = 0; mt < 2; mt++)
#pragma unroll
        for (int h = 0; h < 2; h++) {
            int m = node0 + mb + mt * 16 + (lane >> 2) + 8 * h;
            if (m < Nn) {
                float* op = out + (size_t)m * 256 + bo + cg * 32 + 2 * (lane & 3);
#pragma unroll
                for (int nt = 0; nt < 4; nt++)
                    *(float2*)(op + nt * 8) =
                        make_float2(OA[mt][nt][2 * h], OA[mt][nt][2 * h + 1]);
            }
        }
}

// ---------------- launch ----------------
extern "C" void kernel_launch(void* const* d_in, const int* in_sizes, int n_in,
                              void* d_out, int out_size) {
    const float* x       = (const float*)d_in[0];
    const void*  edges   = (const void*) d_in[1];
    const void*  mask    = (const void*) d_in[2];
    const float* logp    = (const float*)d_in[3];
    const float* means   = (const float*)d_in[4];
    const float* logvars = (const float*)d_in[5];
    const float* W       = (const float*)d_in[6];
    const float* bias    = (const float*)d_in[7];
    float* out = (float*)d_out;

    int Nn = in_sizes[0] / FD;      // 50000
    int E  = in_sizes[1] / 2;       // 1600000
    int nb = (Nn + 1023) / 1024;

    k_detect<<<1, 256>>>((const unsigned char*)mask, (const unsigned int*)edges);
    k_zero<<<(Nn + 255) / 256, 256>>>(Nn);
    k_weights<<<FD, FD>>>(W, means, logvars);
    k_init<<<Nn, 256>>>(x, mask, logp, means, Nn);
    k_hist<<<2048, 256>>>(edges, E);
    k_s1<<<nb, 1024>>>(Nn);
    k_s2<<<1, 32>>>(nb);
    k_s3<<<nb, 1024>>>(Nn, E);
    k_fill<<<2048, 256>>>(edges, E);
    k_gather<<<2960, 256>>>(Nn);

    static int attr_set = 0;
    if (!attr_set) {
        cudaFuncSetAttribute(k_gemm, cudaFuncAttributeMaxDynamicSharedMemorySize, SM_TOTAL);
        attr_set = 1;
    }
    dim3 grid((Nn + 127) / 128, 4);
    k_gemm<<<grid, 256, SM_TOTAL>>>(bias, out, Nn);
}